// round 1
// baseline (speedup 1.0000x reference)
#include <cuda_runtime.h>
#include <cuda_bf16.h>
#include <cstdint>
#include <math.h>

// Problem constants
#define M_TOT 4096      // 2*N*T
#define DIM   512
#define NTOT  2048      // N*T
#define TSPAN 16
#define NEG_INV (1.0f/31.0f)

// Device scratch (no allocs allowed)
__device__ __nv_bfloat16 g_znb[M_TOT * DIM];   // normalized z, bf16 (4 MB)
__device__ float g_rowExp[M_TOT];
__device__ float g_rowNum[M_TOT];

// ---------------------------------------------------------------------------
// Kernel 1: normalize rows -> bf16, zero accumulators
// ---------------------------------------------------------------------------
__global__ void prep_kernel(const float* __restrict__ z) {
    int row = blockIdx.x;
    int tid = threadIdx.x;                      // 128 threads
    const float4 v = ((const float4*)(z + row * DIM))[tid];
    float ss = v.x*v.x + v.y*v.y + v.z*v.z + v.w*v.w;
    #pragma unroll
    for (int o = 16; o; o >>= 1) ss += __shfl_xor_sync(0xffffffffu, ss, o);
    __shared__ float ws[4];
    if ((tid & 31) == 0) ws[tid >> 5] = ss;
    __syncthreads();
    float total = ws[0] + ws[1] + ws[2] + ws[3];
    float norm = fmaxf(sqrtf(total), 1e-8f);
    float rn = 1.0f / norm;
    __nv_bfloat16* out = g_znb + row * DIM + tid * 4;
    out[0] = __float2bfloat16(v.x * rn);
    out[1] = __float2bfloat16(v.y * rn);
    out[2] = __float2bfloat16(v.z * rn);
    out[3] = __float2bfloat16(v.w * rn);
    if (tid == 0) { g_rowExp[row] = 0.0f; g_rowNum[row] = 0.0f; }
}

// ---------------------------------------------------------------------------
// mma / ldmatrix helpers
// ---------------------------------------------------------------------------
__device__ __forceinline__ void ldsm4(uint32_t addr, uint32_t* r) {
    asm volatile("ldmatrix.sync.aligned.m8n8.x4.shared.b16 {%0,%1,%2,%3}, [%4];"
                 : "=r"(r[0]), "=r"(r[1]), "=r"(r[2]), "=r"(r[3]) : "r"(addr));
}
__device__ __forceinline__ void mma16816(float* c, const uint32_t* a, uint32_t b0, uint32_t b1) {
    asm volatile("mma.sync.aligned.m16n8k16.row.col.f32.bf16.bf16.f32 "
                 "{%0,%1,%2,%3}, {%4,%5,%6,%7}, {%8,%9}, {%0,%1,%2,%3};"
                 : "+f"(c[0]), "+f"(c[1]), "+f"(c[2]), "+f"(c[3])
                 : "r"(a[0]), "r"(a[1]), "r"(a[2]), "r"(a[3]), "r"(b0), "r"(b1));
}
__device__ __forceinline__ uint32_t smem_u32(const void* p) {
    return (uint32_t)__cvta_generic_to_shared(p);
}

// ---------------------------------------------------------------------------
// Kernel 2: fused GEMM + exp-sum + same-traj logit sum
// Block: 256 threads. Row stripe BR=64 (A resident in smem, swizzled),
// column split of 1024 cols, inner tiles of 64 cols, K chunks of 64 (double-
// buffered B staging via register prefetch).
// ---------------------------------------------------------------------------
#define BR 64
#define BC 64
#define COLSPLIT 1024
#define A_SMEM_BYTES (BR * DIM * 2)       // 65536, swizzled rows of 1024B
#define B_BUF_BYTES  (BC * 64 * 2)        // 8192 per buffer
#define SMEM_BYTES   (A_SMEM_BYTES + 2 * B_BUF_BYTES)   // 81920

__global__ void __launch_bounds__(256) gemm_kernel() {
    extern __shared__ __align__(16) unsigned char smem[];
    __nv_bfloat16* As = (__nv_bfloat16*)smem;
    unsigned char*  Bs = smem + A_SMEM_BYTES;

    const int rowBase = blockIdx.x * BR;
    const int colBase = blockIdx.y * COLSPLIT;
    const int tid  = threadIdx.x;
    const int lane = tid & 31;
    const int wid  = tid >> 5;
    const int warp_m = wid & 1;       // 2 row groups of 32
    const int warp_n = wid >> 1;      // 4 col groups of 16

    const uint32_t as_u32 = smem_u32(As);
    const uint32_t bs_u32 = smem_u32(Bs);

    // Load A stripe: 64 rows x 512 bf16, SW-style swizzle (16B units, low 3 bits ^ row)
    for (int i = tid; i < BR * 64; i += 256) {
        int r = i >> 6, u = i & 63;
        uint4 v = *(const uint4*)(g_znb + (rowBase + r) * DIM + u * 8);
        int su = (u & ~7) | ((u ^ r) & 7);
        *(uint4*)((unsigned char*)As + r * 1024 + su * 16) = v;
    }

    // B-stage indices for this thread (2 uint4 per chunk)
    const int br_ = tid >> 3, bu_ = tid & 7;
    const int sw0 = br_ * 128 + ((bu_ ^ br_) & 7) * 16;
    const int sw1 = sw0 + 32 * 128;

    float accExp[4] = {0.f, 0.f, 0.f, 0.f};
    float accNum[4] = {0.f, 0.f, 0.f, 0.f};
    const int g = lane >> 2, t = lane & 3;

    for (int tile = 0; tile < COLSPLIT / BC; ++tile) {
        const int colTile = colBase + tile * BC;
        const __nv_bfloat16* bp0 = g_znb + (colTile + br_) * DIM + bu_ * 8;
        const __nv_bfloat16* bp1 = bp0 + 32 * DIM;

        float acc[4][4];
        #pragma unroll
        for (int q = 0; q < 4; ++q)
            #pragma unroll
            for (int i = 0; i < 4; ++i) acc[q][i] = 0.f;

        uint4 p0 = *(const uint4*)(bp0);
        uint4 p1 = *(const uint4*)(bp1);

        #pragma unroll 2
        for (int ch = 0; ch < 8; ++ch) {
            __syncthreads();
            unsigned char* bb = Bs + (ch & 1) * B_BUF_BYTES;
            *(uint4*)(bb + sw0) = p0;
            *(uint4*)(bb + sw1) = p1;
            __syncthreads();
            if (ch < 7) {
                p0 = *(const uint4*)(bp0 + (ch + 1) * 64);
                p1 = *(const uint4*)(bp1 + (ch + 1) * 64);
            }
            const uint32_t bbase = bs_u32 + (ch & 1) * B_BUF_BYTES;
            #pragma unroll
            for (int ks = 0; ks < 4; ++ks) {
                uint32_t a0[4], a1[4], b[4];
                const int ku = ch * 8 + ks * 2 + (lane >> 4);
                {
                    int m = warp_m * 32 + (lane & 15);
                    uint32_t ad = as_u32 + m * 1024 + (((ku & ~7) | ((ku ^ m) & 7)) << 4);
                    ldsm4(ad, a0);
                    m += 16;
                    ad = as_u32 + m * 1024 + (((ku & ~7) | ((ku ^ m) & 7)) << 4);
                    ldsm4(ad, a1);
                }
                {
                    int r  = warp_n * 16 + ((lane >> 4) << 3) + (lane & 7);
                    int kb = ks * 2 + ((lane >> 3) & 1);
                    uint32_t ad = bbase + r * 128 + (((kb ^ r) & 7) << 4);
                    ldsm4(ad, b);
                }
                mma16816(acc[0], a0, b[0], b[1]);   // mt0, nt0
                mma16816(acc[1], a0, b[2], b[3]);   // mt0, nt1
                mma16816(acc[2], a1, b[0], b[1]);   // mt1, nt0
                mma16816(acc[3], a1, b[2], b[3]);   // mt1, nt1
            }
        }

        // Epilogue for this 64x64 tile (register-only)
        #pragma unroll
        for (int mt = 0; mt < 2; ++mt)
            #pragma unroll
            for (int nt = 0; nt < 2; ++nt) {
                const float* a = acc[mt * 2 + nt];
                #pragma unroll
                for (int i = 0; i < 4; ++i) {
                    int R = rowBase + warp_m * 32 + mt * 16 + g + (i >> 1) * 8;
                    int C = colTile + warp_n * 16 + nt * 8 + t * 2 + (i & 1);
                    float lg = a[i] * 10.0f;    // /TEMP
                    if (C != R) {
                        int slot = mt * 2 + (i >> 1);
                        accExp[slot] += __expf(lg);
                        if (((R & 2047) >> 4) == ((C & 2047) >> 4)) accNum[slot] += lg;
                    }
                }
            }
    }

    // Reduce across the 4 lanes sharing the same rows (t dimension)
    #pragma unroll
    for (int o = 1; o <= 2; o <<= 1)
        #pragma unroll
        for (int s = 0; s < 4; ++s) {
            accExp[s] += __shfl_xor_sync(0xffffffffu, accExp[s], o);
            accNum[s] += __shfl_xor_sync(0xffffffffu, accNum[s], o);
        }

    __shared__ float sExp[BR], sNum[BR];
    __syncthreads();
    if (tid < BR) { sExp[tid] = 0.f; sNum[tid] = 0.f; }
    __syncthreads();
    if (t == 0) {
        #pragma unroll
        for (int s = 0; s < 4; ++s) {
            int rl = warp_m * 32 + (s >> 1) * 16 + g + (s & 1) * 8;
            atomicAdd(&sExp[rl], accExp[s]);
            atomicAdd(&sNum[rl], accNum[s]);
        }
    }
    __syncthreads();
    if (tid < BR) {
        atomicAdd(&g_rowExp[rowBase + tid], sExp[tid]);
        atomicAdd(&g_rowNum[rowBase + tid], sNum[tid]);
    }
}

// ---------------------------------------------------------------------------
// Kernel 3: per-row loss + global mean
// ---------------------------------------------------------------------------
__global__ void finalize_kernel(float* __restrict__ out) {
    int tid = threadIdx.x;   // 1024 threads
    float s = 0.f;
    for (int r = tid; r < M_TOT; r += 1024)
        s += g_rowNum[r] * NEG_INV - logf(g_rowExp[r]);
    #pragma unroll
    for (int o = 16; o; o >>= 1) s += __shfl_xor_sync(0xffffffffu, s, o);
    __shared__ float ws[32];
    if ((tid & 31) == 0) ws[tid >> 5] = s;
    __syncthreads();
    if (tid < 32) {
        float v = ws[tid];
        #pragma unroll
        for (int o = 16; o; o >>= 1) v += __shfl_xor_sync(0xffffffffu, v, o);
        if (tid == 0) out[0] = -v / (float)M_TOT;
    }
}

// ---------------------------------------------------------------------------
extern "C" void kernel_launch(void* const* d_in, const int* in_sizes, int n_in,
                              void* d_out, int out_size) {
    // z is the float32 [M, D] input; done is unused (cancels analytically).
    const float* z = (const float*)d_in[0];
    if (n_in > 1 && in_sizes[0] != M_TOT * DIM) z = (const float*)d_in[1];

    cudaFuncSetAttribute(gemm_kernel, cudaFuncAttributeMaxDynamicSharedMemorySize, SMEM_BYTES);

    prep_kernel<<<M_TOT, 128>>>(z);
    gemm_kernel<<<dim3(M_TOT / BR, M_TOT / COLSPLIT), 256, SMEM_BYTES>>>();
    finalize_kernel<<<1, 1024>>>((float*)d_out);
}

// round 2
// speedup vs baseline: 1.4932x; 1.4932x over previous
#include <cuda_runtime.h>
#include <cuda_bf16.h>
#include <cstdint>
#include <math.h>

// Problem constants
#define M_TOT 4096      // 2*N*T
#define DIM   512
#define TSPAN 16
#define NEG_INV (1.0f/31.0f)

// Device scratch (no allocs allowed)
__device__ __nv_bfloat16 g_znb[M_TOT * DIM];   // normalized z, bf16 (4 MB)
__device__ float g_rowExp[M_TOT];
__device__ float g_rowNum[M_TOT];

// ---------------------------------------------------------------------------
// Kernel 1: normalize rows -> bf16 (warp per row), zero exp accumulators
// ---------------------------------------------------------------------------
__global__ void __launch_bounds__(256) prep_kernel(const float* __restrict__ z) {
    const int row  = (blockIdx.x * 256 + threadIdx.x) >> 5;
    const int lane = threadIdx.x & 31;
    const float4* src = (const float4*)(z + row * DIM);
    float4 v[4];
    float ss = 0.f;
    #pragma unroll
    for (int k = 0; k < 4; ++k) {
        v[k] = src[lane + k * 32];
        ss += v[k].x*v[k].x + v[k].y*v[k].y + v[k].z*v[k].z + v[k].w*v[k].w;
    }
    #pragma unroll
    for (int o = 16; o; o >>= 1) ss += __shfl_xor_sync(0xffffffffu, ss, o);
    const float rn = 1.0f / fmaxf(sqrtf(ss), 1e-8f);
    __nv_bfloat162* dst = (__nv_bfloat162*)(g_znb + row * DIM);
    #pragma unroll
    for (int k = 0; k < 4; ++k) {
        dst[lane*2 + k*64 + 0] = __floats2bfloat162_rn(v[k].x * rn, v[k].y * rn);
        dst[lane*2 + k*64 + 1] = __floats2bfloat162_rn(v[k].z * rn, v[k].w * rn);
    }
    if (lane == 0) g_rowExp[row] = 0.0f;
}

// ---------------------------------------------------------------------------
// Kernel 1b: same-trajectory numerator, computed analytically:
//   num_i = 10 * ( zn_i . S_group  -  zn_i . zn_i )
// where S_group = sum of the 32 rows (both views) sharing the trajectory.
// ---------------------------------------------------------------------------
__global__ void __launch_bounds__(256) groupnum_kernel() {
    __shared__ float S[DIM];
    const int grp = blockIdx.x;          // 0..127
    const int tid = threadIdx.x;         // 256 threads; thread handles dims {2t,2t+1}
    float s0 = 0.f, s1 = 0.f;
    #pragma unroll
    for (int r = 0; r < 32; ++r) {
        const int row = grp * TSPAN + (r & 15) + (r >> 4) * (M_TOT/2);
        const __nv_bfloat162 b = *(const __nv_bfloat162*)(g_znb + row * DIM + tid * 2);
        s0 += __bfloat162float(b.x);
        s1 += __bfloat162float(b.y);
    }
    S[tid*2] = s0; S[tid*2+1] = s1;
    __syncthreads();

    const int wid = tid >> 5, lane = tid & 31;
    #pragma unroll
    for (int rr = 0; rr < 4; ++rr) {
        const int r   = wid * 4 + rr;
        const int row = grp * TSPAN + (r & 15) + (r >> 4) * (M_TOT/2);
        float d1 = 0.f, d2 = 0.f;
        #pragma unroll
        for (int j = 0; j < 8; ++j) {
            const int pi = lane + j * 32;                 // bf16x2 pair index
            const __nv_bfloat162 b = *(const __nv_bfloat162*)(g_znb + row * DIM + pi * 2);
            const float z0 = __bfloat162float(b.x), z1 = __bfloat162float(b.y);
            d1 += z0 * S[pi*2] + z1 * S[pi*2+1];
            d2 += z0 * z0 + z1 * z1;
        }
        #pragma unroll
        for (int o = 16; o; o >>= 1) {
            d1 += __shfl_xor_sync(0xffffffffu, d1, o);
            d2 += __shfl_xor_sync(0xffffffffu, d2, o);
        }
        if (lane == 0) g_rowNum[row] = 10.0f * (d1 - d2);
    }
}

// ---------------------------------------------------------------------------
// mma / ldmatrix helpers
// ---------------------------------------------------------------------------
__device__ __forceinline__ void ldsm4(uint32_t addr, uint32_t* r) {
    asm volatile("ldmatrix.sync.aligned.m8n8.x4.shared.b16 {%0,%1,%2,%3}, [%4];"
                 : "=r"(r[0]), "=r"(r[1]), "=r"(r[2]), "=r"(r[3]) : "r"(addr));
}
__device__ __forceinline__ void mma16816(float* c, const uint32_t* a, uint32_t b0, uint32_t b1) {
    asm volatile("mma.sync.aligned.m16n8k16.row.col.f32.bf16.bf16.f32 "
                 "{%0,%1,%2,%3}, {%4,%5,%6,%7}, {%8,%9}, {%0,%1,%2,%3};"
                 : "+f"(c[0]), "+f"(c[1]), "+f"(c[2]), "+f"(c[3])
                 : "r"(a[0]), "r"(a[1]), "r"(a[2]), "r"(a[3]), "r"(b0), "r"(b1));
}
__device__ __forceinline__ uint32_t smem_u32(const void* p) {
    return (uint32_t)__cvta_generic_to_shared(p);
}

// FFMA-only exp(10*a): 2^(a*14.4269504), degree-5 Taylor on [-0.5, 0.5]
__device__ __forceinline__ float exp10x(float a) {
    const float L = 14.4269504f;              // 10 * log2(e)
    const float tk = __fmaf_rn(a, L, 12582912.0f);   // 1.5*2^23 round-to-nearest
    const int   X  = __float_as_int(tk);
    const float kf = tk - 12582912.0f;
    const float f  = __fmaf_rn(a, L, -kf);    // residual, in [-0.5, 0.5]
    float p = 1.3333558e-3f;
    p = __fmaf_rn(p, f, 9.6181291e-3f);
    p = __fmaf_rn(p, f, 5.5504109e-2f);
    p = __fmaf_rn(p, f, 2.4022651e-1f);
    p = __fmaf_rn(p, f, 6.9314718e-1f);
    p = __fmaf_rn(p, f, 1.0f);
    return p * __int_as_float((X << 23) + 0x3F800000);
}

// ---------------------------------------------------------------------------
// Kernel 2: fused GEMM + exp-sum. Block: 256 threads, BR=64 rows resident,
// 512-col split, 64-col inner tiles, double-buffered B staging.
// ---------------------------------------------------------------------------
#define BR 64
#define BC 64
#define COLSPLIT 512
#define A_SMEM_BYTES (BR * DIM * 2)       // 65536, swizzled rows of 1024B
#define B_BUF_BYTES  (BC * 64 * 2)        // 8192 per buffer
#define SMEM_BYTES   (A_SMEM_BYTES + 2 * B_BUF_BYTES)   // 81920

__global__ void __launch_bounds__(256) gemm_kernel() {
    extern __shared__ __align__(16) unsigned char smem[];
    __nv_bfloat16* As = (__nv_bfloat16*)smem;
    unsigned char*  Bs = smem + A_SMEM_BYTES;

    const int rowBase = blockIdx.x * BR;
    const int colBase = blockIdx.y * COLSPLIT;
    const int tid  = threadIdx.x;
    const int lane = tid & 31;
    const int wid  = tid >> 5;
    const int warp_m = wid & 1;       // 2 row groups of 32
    const int warp_n = wid >> 1;      // 4 col groups of 16

    const uint32_t as_u32 = smem_u32(As);
    const uint32_t bs_u32 = smem_u32(Bs);

    // Load A stripe: 64 rows x 512 bf16, swizzled (16B units, low 3 bits ^ row)
    for (int i = tid; i < BR * 64; i += 256) {
        int r = i >> 6, u = i & 63;
        uint4 v = *(const uint4*)(g_znb + (rowBase + r) * DIM + u * 8);
        int su = (u & ~7) | ((u ^ r) & 7);
        *(uint4*)((unsigned char*)As + r * 1024 + su * 16) = v;
    }

    // B-stage indices for this thread (2 uint4 per chunk)
    const int br_ = tid >> 3, bu_ = tid & 7;
    const int sw0 = br_ * 128 + ((bu_ ^ br_) & 7) * 16;
    const int sw1 = sw0 + 32 * 128;

    float accExp[4] = {0.f, 0.f, 0.f, 0.f};
    const int gq = lane >> 2, tq = lane & 3;

    for (int tile = 0; tile < COLSPLIT / BC; ++tile) {
        const int colTile = colBase + tile * BC;
        const __nv_bfloat16* bp0 = g_znb + (colTile + br_) * DIM + bu_ * 8;
        const __nv_bfloat16* bp1 = bp0 + 32 * DIM;

        float acc[4][4];
        #pragma unroll
        for (int q = 0; q < 4; ++q)
            #pragma unroll
            for (int i = 0; i < 4; ++i) acc[q][i] = 0.f;

        uint4 p0 = *(const uint4*)(bp0);
        uint4 p1 = *(const uint4*)(bp1);

        #pragma unroll 2
        for (int ch = 0; ch < 8; ++ch) {
            __syncthreads();
            unsigned char* bb = Bs + (ch & 1) * B_BUF_BYTES;
            *(uint4*)(bb + sw0) = p0;
            *(uint4*)(bb + sw1) = p1;
            __syncthreads();
            if (ch < 7) {
                p0 = *(const uint4*)(bp0 + (ch + 1) * 64);
                p1 = *(const uint4*)(bp1 + (ch + 1) * 64);
            }
            const uint32_t bbase = bs_u32 + (ch & 1) * B_BUF_BYTES;
            #pragma unroll
            for (int ks = 0; ks < 4; ++ks) {
                uint32_t a0[4], a1[4], b[4];
                const int ku = ch * 8 + ks * 2 + (lane >> 4);
                {
                    int m = warp_m * 32 + (lane & 15);
                    uint32_t ad = as_u32 + m * 1024 + (((ku & ~7) | ((ku ^ m) & 7)) << 4);
                    ldsm4(ad, a0);
                    m += 16;
                    ad = as_u32 + m * 1024 + (((ku & ~7) | ((ku ^ m) & 7)) << 4);
                    ldsm4(ad, a1);
                }
                {
                    int r  = warp_n * 16 + ((lane >> 4) << 3) + (lane & 7);
                    int kb = ks * 2 + ((lane >> 3) & 1);
                    uint32_t ad = bbase + r * 128 + (((kb ^ r) & 7) << 4);
                    ldsm4(ad, b);
                }
                mma16816(acc[0], a0, b[0], b[1]);   // mt0, nt0
                mma16816(acc[1], a0, b[2], b[3]);   // mt0, nt1
                mma16816(acc[2], a1, b[0], b[1]);   // mt1, nt0
                mma16816(acc[3], a1, b[2], b[3]);   // mt1, nt1
            }
        }

        // Epilogue: FFMA-only exp, accumulate per-row exp sums in registers
        const bool hasDiag = (colTile == rowBase);
        #pragma unroll
        for (int mt = 0; mt < 2; ++mt)
            #pragma unroll
            for (int nt = 0; nt < 2; ++nt) {
                const float* a = acc[mt * 2 + nt];
                #pragma unroll
                for (int i = 0; i < 4; ++i) {
                    float e = exp10x(a[i]);
                    if (hasDiag) {
                        int dR = warp_m * 32 + mt * 16 + gq + (i >> 1) * 8;
                        int dC = warp_n * 16 + nt * 8 + tq * 2 + (i & 1);
                        if (dR == dC) e = 0.f;
                    }
                    accExp[mt * 2 + (i >> 1)] += e;
                }
            }
    }

    // Reduce across the 4 lanes sharing the same rows (tq dimension)
    #pragma unroll
    for (int o = 1; o <= 2; o <<= 1)
        #pragma unroll
        for (int s = 0; s < 4; ++s)
            accExp[s] += __shfl_xor_sync(0xffffffffu, accExp[s], o);

    __shared__ float sExp[BR];
    __syncthreads();
    if (tid < BR) sExp[tid] = 0.f;
    __syncthreads();
    if (tq == 0) {
        #pragma unroll
        for (int s = 0; s < 4; ++s) {
            int rl = warp_m * 32 + (s >> 1) * 16 + gq + (s & 1) * 8;
            atomicAdd(&sExp[rl], accExp[s]);
        }
    }
    __syncthreads();
    if (tid < BR) atomicAdd(&g_rowExp[rowBase + tid], sExp[tid]);
}

// ---------------------------------------------------------------------------
// Kernel 3: per-row loss + global mean
// ---------------------------------------------------------------------------
__global__ void finalize_kernel(float* __restrict__ out) {
    int tid = threadIdx.x;   // 1024 threads
    float s = 0.f;
    for (int r = tid; r < M_TOT; r += 1024)
        s += g_rowNum[r] * NEG_INV - logf(g_rowExp[r]);
    #pragma unroll
    for (int o = 16; o; o >>= 1) s += __shfl_xor_sync(0xffffffffu, s, o);
    __shared__ float ws[32];
    if ((tid & 31) == 0) ws[tid >> 5] = s;
    __syncthreads();
    if (tid < 32) {
        float v = ws[tid];
        #pragma unroll
        for (int o = 16; o; o >>= 1) v += __shfl_xor_sync(0xffffffffu, v, o);
        if (tid == 0) out[0] = -v / (float)M_TOT;
    }
}

// ---------------------------------------------------------------------------
extern "C" void kernel_launch(void* const* d_in, const int* in_sizes, int n_in,
                              void* d_out, int out_size) {
    // z is the float32 [M, D] input; done is unused (cancels analytically).
    const float* z = (const float*)d_in[0];
    if (n_in > 1 && in_sizes[0] != M_TOT * DIM) z = (const float*)d_in[1];

    cudaFuncSetAttribute(gemm_kernel, cudaFuncAttributeMaxDynamicSharedMemorySize, SMEM_BYTES);

    prep_kernel<<<M_TOT / 8, 256>>>(z);
    groupnum_kernel<<<128, 256>>>();
    gemm_kernel<<<dim3(M_TOT / BR, M_TOT / COLSPLIT), 256, SMEM_BYTES>>>();
    finalize_kernel<<<1, 1024>>>((float*)d_out);
}

// round 3
// speedup vs baseline: 2.9388x; 1.9681x over previous
#include <cuda_runtime.h>
#include <cuda_bf16.h>
#include <cstdint>
#include <math.h>

// Problem constants
#define M_TOT 4096      // 2*N*T
#define DIM   512
#define TSPAN 16
#define NEG_INV (1.0f/31.0f)

// Device scratch (no allocs allowed)
__device__ __nv_bfloat16 g_znb[M_TOT * DIM];   // normalized z, bf16 (4 MB)
__device__ float g_rowExp[M_TOT];
__device__ float g_rowNum[M_TOT];

// ---------------------------------------------------------------------------
// Kernel 1: normalize rows -> bf16 (warp per row), zero exp accumulators
// ---------------------------------------------------------------------------
__global__ void __launch_bounds__(256) prep_kernel(const float* __restrict__ z) {
    const int row  = (blockIdx.x * 256 + threadIdx.x) >> 5;
    const int lane = threadIdx.x & 31;
    const float4* src = (const float4*)(z + row * DIM);
    float4 v[4];
    float ss = 0.f;
    #pragma unroll
    for (int k = 0; k < 4; ++k) {
        v[k] = src[lane + k * 32];
        ss += v[k].x*v[k].x + v[k].y*v[k].y + v[k].z*v[k].z + v[k].w*v[k].w;
    }
    #pragma unroll
    for (int o = 16; o; o >>= 1) ss += __shfl_xor_sync(0xffffffffu, ss, o);
    const float rn = 1.0f / fmaxf(sqrtf(ss), 1e-8f);
    __nv_bfloat162* dst = (__nv_bfloat162*)(g_znb + row * DIM);
    #pragma unroll
    for (int k = 0; k < 4; ++k) {
        dst[lane*2 + k*64 + 0] = __floats2bfloat162_rn(v[k].x * rn, v[k].y * rn);
        dst[lane*2 + k*64 + 1] = __floats2bfloat162_rn(v[k].z * rn, v[k].w * rn);
    }
    if (lane == 0) g_rowExp[row] = 0.0f;
}

// ---------------------------------------------------------------------------
// Kernel 1b: same-trajectory numerator, computed analytically:
//   num_i = 10 * ( zn_i . S_group  -  zn_i . zn_i )
// ---------------------------------------------------------------------------
__global__ void __launch_bounds__(256) groupnum_kernel() {
    __shared__ float S[DIM];
    const int grp = blockIdx.x;          // 0..127
    const int tid = threadIdx.x;
    float s0 = 0.f, s1 = 0.f;
    #pragma unroll
    for (int r = 0; r < 32; ++r) {
        const int row = grp * TSPAN + (r & 15) + (r >> 4) * (M_TOT/2);
        const __nv_bfloat162 b = *(const __nv_bfloat162*)(g_znb + row * DIM + tid * 2);
        s0 += __bfloat162float(b.x);
        s1 += __bfloat162float(b.y);
    }
    S[tid*2] = s0; S[tid*2+1] = s1;
    __syncthreads();

    const int wid = tid >> 5, lane = tid & 31;
    #pragma unroll
    for (int rr = 0; rr < 4; ++rr) {
        const int r   = wid * 4 + rr;
        const int row = grp * TSPAN + (r & 15) + (r >> 4) * (M_TOT/2);
        float d1 = 0.f, d2 = 0.f;
        #pragma unroll
        for (int j = 0; j < 8; ++j) {
            const int pi = lane + j * 32;
            const __nv_bfloat162 b = *(const __nv_bfloat162*)(g_znb + row * DIM + pi * 2);
            const float z0 = __bfloat162float(b.x), z1 = __bfloat162float(b.y);
            d1 += z0 * S[pi*2] + z1 * S[pi*2+1];
            d2 += z0 * z0 + z1 * z1;
        }
        #pragma unroll
        for (int o = 16; o; o >>= 1) {
            d1 += __shfl_xor_sync(0xffffffffu, d1, o);
            d2 += __shfl_xor_sync(0xffffffffu, d2, o);
        }
        if (lane == 0) g_rowNum[row] = 10.0f * (d1 - d2);
    }
}

// ---------------------------------------------------------------------------
// helpers
// ---------------------------------------------------------------------------
__device__ __forceinline__ void ldsm4(uint32_t addr, uint32_t* r) {
    asm volatile("ldmatrix.sync.aligned.m8n8.x4.shared.b16 {%0,%1,%2,%3}, [%4];"
                 : "=r"(r[0]), "=r"(r[1]), "=r"(r[2]), "=r"(r[3]) : "r"(addr));
}
__device__ __forceinline__ void mma16816(float* c, const uint32_t* a, uint32_t b0, uint32_t b1) {
    asm volatile("mma.sync.aligned.m16n8k16.row.col.f32.bf16.bf16.f32 "
                 "{%0,%1,%2,%3}, {%4,%5,%6,%7}, {%8,%9}, {%0,%1,%2,%3};"
                 : "+f"(c[0]), "+f"(c[1]), "+f"(c[2]), "+f"(c[3])
                 : "r"(a[0]), "r"(a[1]), "r"(a[2]), "r"(a[3]), "r"(b0), "r"(b1));
}
__device__ __forceinline__ uint32_t smem_u32(const void* p) {
    return (uint32_t)__cvta_generic_to_shared(p);
}
#define CP_ASYNC16(dst, src) \
    asm volatile("cp.async.cg.shared.global [%0], [%1], 16;\n" :: "r"(dst), "l"(src))
#define CP_COMMIT() asm volatile("cp.async.commit_group;\n" ::: "memory")
#define CP_WAIT2()  asm volatile("cp.async.wait_group 2;\n" ::: "memory")

// FFMA-only exp(10*a): 2^(a*14.4269504), degree-5 poly on [-0.5, 0.5]
__device__ __forceinline__ float exp10x(float a) {
    const float L = 14.4269504f;
    const float tk = __fmaf_rn(a, L, 12582912.0f);
    const int   X  = __float_as_int(tk);
    const float kf = tk - 12582912.0f;
    const float f  = __fmaf_rn(a, L, -kf);
    float p = 1.3333558e-3f;
    p = __fmaf_rn(p, f, 9.6181291e-3f);
    p = __fmaf_rn(p, f, 5.5504109e-2f);
    p = __fmaf_rn(p, f, 2.4022651e-1f);
    p = __fmaf_rn(p, f, 6.9314718e-1f);
    p = __fmaf_rn(p, f, 1.0f);
    return p * __int_as_float((X << 23) + 0x3F800000);
}

// ---------------------------------------------------------------------------
// Kernel 2: symmetric fused GEMM + exp-sum.
// Upper-triangular 128x128 tiles only (528 blocks). Off-diagonal tiles
// scatter exp() to both block-row (row sums) and block-col (col sums,
// using exp(g_ij)==exp(g_ji)). 3-stage cp.async pipeline, K-chunks of 64.
// ---------------------------------------------------------------------------
#define BT 128
#define KC 64
#define STAGE_BYTES 32768                  // A 16KB + B 16KB per stage
#define SMEM_BYTES  (3 * STAGE_BYTES)      // 98304

__global__ void __launch_bounds__(256, 2) gemm_kernel() {
    extern __shared__ __align__(16) unsigned char smem[];

    // Decode upper-triangular tile index: f(b) = b*(65-b)/2
    int idx = blockIdx.x;
    int bi = (int)(32.5f - sqrtf(1056.25f - 2.0f * (float)idx));
    if (bi < 0) bi = 0; if (bi > 31) bi = 31;
    while (bi * (65 - bi) / 2 > idx) --bi;
    while ((bi + 1) * (64 - bi) / 2 <= idx) ++bi;
    const int bj = bi + (idx - bi * (65 - bi) / 2);
    const bool diag = (bi == bj);
    const int rowBase = bi * BT, colBase = bj * BT;

    const int tid = threadIdx.x, lane = tid & 31, wid = tid >> 5;
    const int warp_m = wid & 1;        // 2 x 64 rows
    const int warp_n = wid >> 1;       // 4 x 32 cols
    const uint32_t sbase = smem_u32(smem);

    // Loader: thread -> row lr, 4 consecutive 16B units starting at lu
    const int lr = tid >> 1;
    const int lu = (tid & 1) * 4;
    const __nv_bfloat16* gA = g_znb + (rowBase + lr) * DIM + lu * 8;
    const __nv_bfloat16* gB = g_znb + (colBase + lr) * DIM + lu * 8;
    uint32_t dstA[4];
    #pragma unroll
    for (int u = 0; u < 4; ++u)
        dstA[u] = sbase + lr * 128 + (((lu + u) ^ (lr & 7)) << 4);

    float acc[4][4][4];
    #pragma unroll
    for (int a = 0; a < 4; ++a)
        #pragma unroll
        for (int b = 0; b < 4; ++b)
            #pragma unroll
            for (int i = 0; i < 4; ++i) acc[a][b][i] = 0.f;

    // Prologue: stage chunks 0, 1
    #pragma unroll
    for (int ch = 0; ch < 2; ++ch) {
        const uint32_t so = ch * STAGE_BYTES;
        #pragma unroll
        for (int u = 0; u < 4; ++u) CP_ASYNC16(dstA[u] + so,         gA + ch * KC + u * 8);
        #pragma unroll
        for (int u = 0; u < 4; ++u) CP_ASYNC16(dstA[u] + so + 16384, gB + ch * KC + u * 8);
        CP_COMMIT();
    }

    for (int ch = 0; ch < 8; ++ch) {
        if (ch + 2 < 8) {
            const uint32_t so = ((ch + 2) % 3) * STAGE_BYTES;
            #pragma unroll
            for (int u = 0; u < 4; ++u) CP_ASYNC16(dstA[u] + so,         gA + (ch + 2) * KC + u * 8);
            #pragma unroll
            for (int u = 0; u < 4; ++u) CP_ASYNC16(dstA[u] + so + 16384, gB + (ch + 2) * KC + u * 8);
        }
        CP_COMMIT();            // every iter -> uniform wait bound
        CP_WAIT2();             // chunk ch resident
        __syncthreads();

        const uint32_t Ab = sbase + (ch % 3) * STAGE_BYTES;
        const uint32_t Bb = Ab + 16384;
        #pragma unroll
        for (int ks = 0; ks < 4; ++ks) {
            uint32_t afr[4][4], bfr[2][4];
            #pragma unroll
            for (int mt = 0; mt < 4; ++mt) {
                const int m = warp_m * 64 + mt * 16 + (lane & 15);
                const int u = ks * 2 + (lane >> 4);
                ldsm4(Ab + m * 128 + (((u ^ (m & 7))) << 4), afr[mt]);
            }
            #pragma unroll
            for (int np = 0; np < 2; ++np) {
                const int n = warp_n * 32 + np * 16 + ((lane >> 4) << 3) + (lane & 7);
                const int u = ks * 2 + ((lane >> 3) & 1);
                ldsm4(Bb + n * 128 + (((u ^ (n & 7))) << 4), bfr[np]);
            }
            #pragma unroll
            for (int mt = 0; mt < 4; ++mt)
                #pragma unroll
                for (int np = 0; np < 2; ++np) {
                    mma16816(acc[mt][np * 2 + 0], afr[mt], bfr[np][0], bfr[np][1]);
                    mma16816(acc[mt][np * 2 + 1], afr[mt], bfr[np][2], bfr[np][3]);
                }
        }
        __syncthreads();        // protect stage about to be overwritten
    }

    // ---- Epilogue: exp + row sums (and col sums for off-diagonal tiles) ----
    const int gq = lane >> 2, tq = lane & 3;
    float accRow[4][2];
    float accCol[4][2];
    #pragma unroll
    for (int a = 0; a < 4; ++a) { accRow[a][0]=accRow[a][1]=0.f; accCol[a][0]=accCol[a][1]=0.f; }

    #pragma unroll
    for (int mt = 0; mt < 4; ++mt)
        #pragma unroll
        for (int nn = 0; nn < 4; ++nn)
            #pragma unroll
            for (int i = 0; i < 4; ++i) {
                float e = exp10x(acc[mt][nn][i]);
                if (diag) {
                    const int dR = warp_m * 64 + mt * 16 + gq + (i >> 1) * 8;
                    const int dC = warp_n * 32 + nn * 8 + tq * 2 + (i & 1);
                    if (dR == dC) e = 0.f;
                }
                accRow[mt][i >> 1] += e;
                accCol[nn][i & 1]  += e;
            }

    // row sums: reduce over tq (lanes xor 1,2)
    #pragma unroll
    for (int o = 1; o <= 2; o <<= 1)
        #pragma unroll
        for (int mt = 0; mt < 4; ++mt) {
            accRow[mt][0] += __shfl_xor_sync(0xffffffffu, accRow[mt][0], o);
            accRow[mt][1] += __shfl_xor_sync(0xffffffffu, accRow[mt][1], o);
        }
    // col sums: reduce over gq (lanes xor 4,8,16)
    if (!diag) {
        #pragma unroll
        for (int o = 4; o <= 16; o <<= 1)
            #pragma unroll
            for (int nn = 0; nn < 4; ++nn) {
                accCol[nn][0] += __shfl_xor_sync(0xffffffffu, accCol[nn][0], o);
                accCol[nn][1] += __shfl_xor_sync(0xffffffffu, accCol[nn][1], o);
            }
    }

    __shared__ float sRow[BT], sCol[BT];
    __syncthreads();
    if (tid < BT) { sRow[tid] = 0.f; sCol[tid] = 0.f; }
    __syncthreads();
    if (tq == 0) {
        #pragma unroll
        for (int mt = 0; mt < 4; ++mt)
            #pragma unroll
            for (int ih = 0; ih < 2; ++ih)
                atomicAdd(&sRow[warp_m * 64 + mt * 16 + gq + ih * 8], accRow[mt][ih]);
    }
    if (!diag && gq == 0) {
        #pragma unroll
        for (int nn = 0; nn < 4; ++nn)
            #pragma unroll
            for (int j = 0; j < 2; ++j)
                atomicAdd(&sCol[warp_n * 32 + nn * 8 + tq * 2 + j], accCol[nn][j]);
    }
    __syncthreads();
    if (tid < BT) {
        atomicAdd(&g_rowExp[rowBase + tid], sRow[tid]);
        if (!diag) atomicAdd(&g_rowExp[colBase + tid], sCol[tid]);
    }
}

// ---------------------------------------------------------------------------
// Kernel 3: per-row loss + global mean
// ---------------------------------------------------------------------------
__global__ void finalize_kernel(float* __restrict__ out) {
    int tid = threadIdx.x;   // 1024 threads
    float s = 0.f;
    #pragma unroll
    for (int k = 0; k < 4; ++k) {
        int r = tid + k * 1024;
        s += g_rowNum[r] * NEG_INV - __logf(g_rowExp[r]);
    }
    #pragma unroll
    for (int o = 16; o; o >>= 1) s += __shfl_xor_sync(0xffffffffu, s, o);
    __shared__ float ws[32];
    if ((tid & 31) == 0) ws[tid >> 5] = s;
    __syncthreads();
    if (tid < 32) {
        float v = ws[tid];
        #pragma unroll
        for (int o = 16; o; o >>= 1) v += __shfl_xor_sync(0xffffffffu, v, o);
        if (tid == 0) out[0] = -v / (float)M_TOT;
    }
}

// ---------------------------------------------------------------------------
extern "C" void kernel_launch(void* const* d_in, const int* in_sizes, int n_in,
                              void* d_out, int out_size) {
    const float* z = (const float*)d_in[0];
    if (n_in > 1 && in_sizes[0] != M_TOT * DIM) z = (const float*)d_in[1];

    cudaFuncSetAttribute(gemm_kernel, cudaFuncAttributeMaxDynamicSharedMemorySize, SMEM_BYTES);

    prep_kernel<<<M_TOT / 8, 256>>>(z);
    groupnum_kernel<<<128, 256>>>();
    gemm_kernel<<<528, 256, SMEM_BYTES>>>();
    finalize_kernel<<<1, 1024>>>((float*)d_out);
}